// round 1
// baseline (speedup 1.0000x reference)
#include <cuda_runtime.h>
#include <cstdint>

// Problem constants
#define BDIM 2
#define LSEQ 8192
#define CDIM 512
#define KWIN 17
#define HALFK 8
#define NTOK (BDIM * LSEQ)      // 16384

// Scratch (no cudaMalloc allowed)
__device__ float g_qkv[(size_t)NTOK * 3 * CDIM];   // 96 MB
__device__ float g_att[(size_t)NTOK * CDIM];       // 32 MB

// ---------------------------------------------------------------------------
// Tiled fp32 GEMM: C[M,N] = A[M,K] * B[K,N], all row-major.
// BM=BN=128, BK=16, 256 threads, 8x8 per thread. Dims assumed divisible.
// ---------------------------------------------------------------------------
#define BM 128
#define BN 128
#define BK 16
#define TM 8
#define TN 8

__global__ __launch_bounds__(256) void gemm_f32(const float* __restrict__ A,
                                                const float* __restrict__ B,
                                                float* __restrict__ C,
                                                int M, int N, int Kd)
{
    __shared__ float As[BK][BM + 4];
    __shared__ float Bs[BK][BN];

    const int tid = threadIdx.x;
    const int tx = tid & 15;          // 0..15 -> N direction
    const int ty = tid >> 4;          // 0..15 -> M direction

    const int bm = blockIdx.y * BM;
    const int bn = blockIdx.x * BN;

    const float* Ab = A + (size_t)bm * Kd;
    const float* Bb = B + bn;

    float acc[TM][TN];
    #pragma unroll
    for (int i = 0; i < TM; i++)
        #pragma unroll
        for (int j = 0; j < TN; j++) acc[i][j] = 0.f;

    const int arow = tid >> 2;            // 0..63
    const int acol = (tid & 3) * 4;       // 0,4,8,12
    const int brow = tid >> 5;            // 0..7
    const int bcol = (tid & 31) * 4;      // 0..124

    for (int k0 = 0; k0 < Kd; k0 += BK) {
        // Load A tile (transposed into As[k][m]) — 2 float4 per thread
        #pragma unroll
        for (int r = 0; r < 2; r++) {
            const int m = arow + r * 64;
            float4 va = *(const float4*)(Ab + (size_t)m * Kd + k0 + acol);
            As[acol + 0][m] = va.x;
            As[acol + 1][m] = va.y;
            As[acol + 2][m] = va.z;
            As[acol + 3][m] = va.w;
        }
        // Load B tile (direct) — 2 float4 per thread
        #pragma unroll
        for (int r = 0; r < 2; r++) {
            const int kr = brow + r * 8;
            *(float4*)(&Bs[kr][bcol]) =
                *(const float4*)(Bb + (size_t)(k0 + kr) * N + bcol);
        }
        __syncthreads();

        #pragma unroll
        for (int kk = 0; kk < BK; kk++) {
            float a[TM], b[TN];
            #pragma unroll
            for (int i = 0; i < TM; i++) a[i] = As[kk][ty * TM + i];
            #pragma unroll
            for (int j = 0; j < TN; j++) b[j] = Bs[kk][tx * TN + j];
            #pragma unroll
            for (int i = 0; i < TM; i++)
                #pragma unroll
                for (int j = 0; j < TN; j++)
                    acc[i][j] += a[i] * b[j];
        }
        __syncthreads();
    }

    float* Cb = C + (size_t)(bm + ty * TM) * N + bn + tx * TN;
    #pragma unroll
    for (int i = 0; i < TM; i++) {
        #pragma unroll
        for (int j = 0; j < TN; j += 4) {
            *(float4*)(Cb + (size_t)i * N + j) =
                make_float4(acc[i][j], acc[i][j + 1], acc[i][j + 2], acc[i][j + 3]);
        }
    }
}

// ---------------------------------------------------------------------------
// Warp-per-token windowed attention, fused with width-GEMV, soft mask,
// softmax and the "+ v" residual. Writes g_att = attn@v_win + v.
// ---------------------------------------------------------------------------
__global__ __launch_bounds__(256) void attn_kernel(const float* __restrict__ x,
                                                   const float* __restrict__ w_width,
                                                   const float* __restrict__ b_width,
                                                   float* __restrict__ att)
{
    const int gwarp = (blockIdx.x * blockDim.x + threadIdx.x) >> 5;
    const int lane = threadIdx.x & 31;
    if (gwarp >= NTOK) return;

    const int b = gwarp >> 13;            // / LSEQ
    const int l = gwarp & (LSEQ - 1);

    const float* qkv = g_qkv;
    const float* qrow = qkv + (size_t)gwarp * 3 * CDIM;   // q at offset 0

    // load q (16 floats per lane, coalesced)
    float q[16];
    #pragma unroll
    for (int i = 0; i < 16; i++) q[i] = qrow[lane + 32 * i];

    // width = sigmoid(x_row . w_width + b) * (K-1) + 1
    const float* xrow = x + (size_t)gwarp * CDIM;
    float wsum = 0.f;
    #pragma unroll
    for (int i = 0; i < 16; i++)
        wsum += xrow[lane + 32 * i] * w_width[lane + 32 * i];
    #pragma unroll
    for (int o = 16; o > 0; o >>= 1) wsum += __shfl_xor_sync(0xffffffffu, wsum, o);
    const float width = 1.f / (1.f + expf(-(wsum + b_width[0]))) * (float)(KWIN - 1) + 1.f;

    // raw scores (zero-padded outside sequence, as in reference)
    float sc[KWIN];
    #pragma unroll
    for (int j = 0; j < KWIN; j++) {
        const int row = l + j - HALFK;
        float s = 0.f;
        if (row >= 0 && row < LSEQ) {
            const float* krow = qkv + ((size_t)(b * LSEQ + row) * 3 + 1) * CDIM;
            #pragma unroll
            for (int i = 0; i < 16; i++) s += q[i] * krow[lane + 32 * i];
        }
        #pragma unroll
        for (int o = 16; o > 0; o >>= 1) s += __shfl_xor_sync(0xffffffffu, s, o);
        sc[j] = s;
    }

    // scale + soft mask + softmax
    const float scale = 0.044194173824159216f;  // 512^-0.5
    float mx = -1e30f;
    #pragma unroll
    for (int j = 0; j < KWIN; j++) {
        const float rel = fabsf((float)j - (float)HALFK);
        const float m = 1.f / (1.f + expf(-(width - rel) * 5.f));
        sc[j] = sc[j] * scale - (1.f - m) * 10000.f;
        mx = fmaxf(mx, sc[j]);
    }
    float denom = 0.f;
    #pragma unroll
    for (int j = 0; j < KWIN; j++) {
        sc[j] = expf(sc[j] - mx);
        denom += sc[j];
    }
    const float inv = 1.f / denom;

    // out = attn @ v_win + v_self
    float acc[16];
    const float* vself = qkv + ((size_t)gwarp * 3 + 2) * CDIM;
    #pragma unroll
    for (int i = 0; i < 16; i++) acc[i] = vself[lane + 32 * i];

    #pragma unroll
    for (int j = 0; j < KWIN; j++) {
        const int row = l + j - HALFK;
        if (row < 0 || row >= LSEQ) continue;
        const float a = sc[j] * inv;
        const float* vrow = qkv + ((size_t)(b * LSEQ + row) * 3 + 2) * CDIM;
        #pragma unroll
        for (int i = 0; i < 16; i++) acc[i] += a * vrow[lane + 32 * i];
    }

    float* orow = att + (size_t)gwarp * CDIM;
    #pragma unroll
    for (int i = 0; i < 16; i++) orow[lane + 32 * i] = acc[i];
}

// ---------------------------------------------------------------------------
extern "C" void kernel_launch(void* const* d_in, const int* in_sizes, int n_in,
                              void* d_out, int out_size)
{
    const float* x       = (const float*)d_in[0];  // (2, 8192, 512)
    const float* w_qkv   = (const float*)d_in[1];  // (512, 1536)
    const float* w_width = (const float*)d_in[2];  // (512, 1)
    const float* b_width = (const float*)d_in[3];  // (1,)
    const float* w_out   = (const float*)d_in[4];  // (512, 512)
    float* out = (float*)d_out;                    // (2, 8192, 512)

    float* qkv; cudaGetSymbolAddress((void**)&qkv, g_qkv);
    float* att; cudaGetSymbolAddress((void**)&att, g_att);

    // 1) qkv = x @ w_qkv       M=16384, N=1536, K=512
    {
        dim3 grid(3 * CDIM / BN, NTOK / BM);
        gemm_f32<<<grid, 256>>>(x, w_qkv, qkv, NTOK, 3 * CDIM, CDIM);
    }

    // 2) fused windowed attention -> att = attn@v_win + v
    {
        const int warps_per_block = 8;
        const int blocks = NTOK / warps_per_block;
        attn_kernel<<<blocks, warps_per_block * 32>>>(x, w_width, b_width, att);
    }

    // 3) out = att @ w_out      M=16384, N=512, K=512
    {
        dim3 grid(CDIM / BN, NTOK / BM);
        gemm_f32<<<grid, 256>>>(att, w_out, out, NTOK, CDIM, CDIM);
    }
}

// round 3
// speedup vs baseline: 1.9179x; 1.9179x over previous
#include <cuda_runtime.h>
#include <cuda_bf16.h>
#include <cstdint>

// Problem constants
#define BDIM 2
#define LSEQ 8192
#define CDIM 512
#define KWIN 17
#define HALFK 8
#define NTOK (BDIM * LSEQ)      // 16384

// ---------------------------------------------------------------------------
// Scratch (__device__ globals; no cudaMalloc allowed)
// ---------------------------------------------------------------------------
__device__ float          g_qkv[(size_t)NTOK * 3 * CDIM];     // 96 MB fp32
__device__ __nv_bfloat16  g_xhi[(size_t)NTOK * CDIM];
__device__ __nv_bfloat16  g_xlo[(size_t)NTOK * CDIM];
__device__ __nv_bfloat16  g_ahi[(size_t)NTOK * CDIM];
__device__ __nv_bfloat16  g_alo[(size_t)NTOK * CDIM];
__device__ __nv_bfloat16  g_wqhi[(size_t)3 * CDIM * CDIM];    // [1536][512] = w_qkv^T
__device__ __nv_bfloat16  g_wqlo[(size_t)3 * CDIM * CDIM];
__device__ __nv_bfloat16  g_wohi[(size_t)CDIM * CDIM];        // [512][512]  = w_out^T
__device__ __nv_bfloat16  g_wolo[(size_t)CDIM * CDIM];

// ---------------------------------------------------------------------------
// helpers
// ---------------------------------------------------------------------------
__device__ __forceinline__ uint32_t smem_u32(const void* p) {
    uint32_t a;
    asm("{ .reg .u64 t; cvta.to.shared.u64 t, %1; cvt.u32.u64 %0, t; }" : "=r"(a) : "l"(p));
    return a;
}
__device__ __forceinline__ void cp16(uint32_t dst, const void* src) {
    asm volatile("cp.async.cg.shared.global [%0], [%1], 16;" :: "r"(dst), "l"(src));
}
__device__ __forceinline__ void ldsm_x4(uint32_t* r, uint32_t addr) {
    asm volatile("ldmatrix.sync.aligned.m8n8.x4.shared.b16 {%0,%1,%2,%3}, [%4];"
                 : "=r"(r[0]), "=r"(r[1]), "=r"(r[2]), "=r"(r[3]) : "r"(addr));
}
__device__ __forceinline__ void ldsm_x2(uint32_t* r, uint32_t addr) {
    asm volatile("ldmatrix.sync.aligned.m8n8.x2.shared.b16 {%0,%1}, [%2];"
                 : "=r"(r[0]), "=r"(r[1]) : "r"(addr));
}
__device__ __forceinline__ void mma_bf16(float* c, const uint32_t* a, const uint32_t* b) {
    asm volatile(
        "mma.sync.aligned.m16n8k16.row.col.f32.bf16.bf16.f32 "
        "{%0,%1,%2,%3}, {%4,%5,%6,%7}, {%8,%9}, {%0,%1,%2,%3};"
        : "+f"(c[0]), "+f"(c[1]), "+f"(c[2]), "+f"(c[3])
        : "r"(a[0]), "r"(a[1]), "r"(a[2]), "r"(a[3]), "r"(b[0]), "r"(b[1]));
}

// ---------------------------------------------------------------------------
// Split-bf16 GEMM via mma.sync.  C[M,Ntot] fp32 = (Ahi+Alo)[M,512] @ (B)^T,
// B* stored [Ntot, 512] row-major bf16.  D = Ahi*Bhi + Ahi*Blo + Alo*Bhi.
// Block 128x128, 8 warps (2x4), warp 64x32, BK=32 double-buffered cp.async.
// SMEM rows padded to 80B pitch -> conflict-free ldmatrix.
// ---------------------------------------------------------------------------
#define GK       512
#define BK       32
#define NSTG     (GK / BK)          // 16
#define PITCH    80                 // bytes per 32-bf16 row (64B data + 16B pad)
#define A_SZ     (128 * PITCH)      // 10240
#define STG_SZ   (4 * A_SZ)         // Ahi|Alo|Bhi|Blo = 40960
#define GEMM_SMEM (2 * STG_SZ)      // 81920

__global__ __launch_bounds__(256) void gemm_mma(
    const __nv_bfloat16* __restrict__ Ahi, const __nv_bfloat16* __restrict__ Alo,
    const __nv_bfloat16* __restrict__ Bhi, const __nv_bfloat16* __restrict__ Blo,
    float* __restrict__ C, int Ntot)
{
    extern __shared__ char smem[];
    const uint32_t sb = smem_u32(smem);
    const int tid  = threadIdx.x;
    const int wid  = tid >> 5;
    const int lane = tid & 31;
    const int bm = blockIdx.y * 128;
    const int bn = blockIdx.x * 128;
    const int warp_m = (wid >> 2) * 64;     // 0 or 64
    const int warp_n = (wid & 3) * 32;      // 0,32,64,96

    // ---- async stage loader ----
    const int lrow = tid >> 2;              // 0..63
    const int lc16 = (tid & 3) * 16;        // byte col 0..48
    auto load_stage = [&](int s, int b) {
        const int k0 = s * BK;
        const uint32_t buf = sb + (uint32_t)b * STG_SZ;
        #pragma unroll
        for (int r = 0; r < 2; r++) {
            const int row = lrow + r * 64;
            const uint32_t off = (uint32_t)(row * PITCH + lc16);
            const size_t ga = (size_t)(bm + row) * GK + k0 + (lc16 >> 1);
            const size_t gb = (size_t)(bn + row) * GK + k0 + (lc16 >> 1);
            cp16(buf + off,            Ahi + ga);
            cp16(buf + A_SZ + off,     Alo + ga);
            cp16(buf + 2 * A_SZ + off, Bhi + gb);
            cp16(buf + 3 * A_SZ + off, Blo + gb);
        }
        asm volatile("cp.async.commit_group;" ::: "memory");
    };

    float acc[4][4][4];                     // [mi][ni][frag]
    #pragma unroll
    for (int mi = 0; mi < 4; mi++)
        #pragma unroll
        for (int ni = 0; ni < 4; ni++)
            #pragma unroll
            for (int f = 0; f < 4; f++) acc[mi][ni][f] = 0.f;

    // ldmatrix lane address components (within a stage buffer)
    const uint32_t aLane = (uint32_t)((warp_m + (lane & 15)) * PITCH + ((lane >> 4) & 1) * 16);
    const uint32_t bLane = (uint32_t)((warp_n + (lane & 7)) * PITCH + ((lane >> 3) & 1) * 16);

    load_stage(0, 0);
    load_stage(1, 1);

    for (int s = 0; s < NSTG; s++) {
        const int b = s & 1;
        if (s + 1 < NSTG) asm volatile("cp.async.wait_group 1;" ::: "memory");
        else              asm volatile("cp.async.wait_group 0;" ::: "memory");
        __syncthreads();

        const uint32_t buf = sb + (uint32_t)b * STG_SZ;
        #pragma unroll
        for (int kk = 0; kk < 2; kk++) {            // two k16 steps per stage
            const uint32_t ko = (uint32_t)(kk * 32);
            uint32_t af[4][4], bfh[4][2], bfl[4][2];
            #pragma unroll
            for (int mi = 0; mi < 4; mi++)
                ldsm_x4(af[mi], buf + aLane + (uint32_t)(mi * 16 * PITCH) + ko);          // Ahi
            #pragma unroll
            for (int ni = 0; ni < 4; ni++) {
                ldsm_x2(bfh[ni], buf + 2 * A_SZ + bLane + (uint32_t)(ni * 8 * PITCH) + ko); // Bhi
                ldsm_x2(bfl[ni], buf + 3 * A_SZ + bLane + (uint32_t)(ni * 8 * PITCH) + ko); // Blo
            }
            #pragma unroll
            for (int mi = 0; mi < 4; mi++)
                #pragma unroll
                for (int ni = 0; ni < 4; ni++) {
                    mma_bf16(acc[mi][ni], af[mi], bfh[ni]);   // hi*hi
                    mma_bf16(acc[mi][ni], af[mi], bfl[ni]);   // hi*lo
                }
            #pragma unroll
            for (int mi = 0; mi < 4; mi++)
                ldsm_x4(af[mi], buf + A_SZ + aLane + (uint32_t)(mi * 16 * PITCH) + ko);   // Alo
            #pragma unroll
            for (int mi = 0; mi < 4; mi++)
                #pragma unroll
                for (int ni = 0; ni < 4; ni++)
                    mma_bf16(acc[mi][ni], af[mi], bfh[ni]);   // lo*hi
        }
        __syncthreads();
        if (s + 2 < NSTG) load_stage(s + 2, b);
    }

    // ---- epilogue: fp32 direct store ----
    const int er = lane >> 2;            // 0..7
    const int ec = (lane & 3) * 2;       // 0,2,4,6
    #pragma unroll
    for (int mi = 0; mi < 4; mi++) {
        #pragma unroll
        for (int ni = 0; ni < 4; ni++) {
            float* p0 = C + (size_t)(bm + warp_m + mi * 16 + er) * Ntot + bn + warp_n + ni * 8 + ec;
            *(float2*)p0                    = make_float2(acc[mi][ni][0], acc[mi][ni][1]);
            *(float2*)(p0 + (size_t)8 * Ntot) = make_float2(acc[mi][ni][2], acc[mi][ni][3]);
        }
    }
}

// ---------------------------------------------------------------------------
// fp32 -> (hi, lo) bf16 split, elementwise
// ---------------------------------------------------------------------------
__global__ __launch_bounds__(256) void split_kernel(const float* __restrict__ src,
                                                    __nv_bfloat16* __restrict__ hi,
                                                    __nv_bfloat16* __restrict__ lo)
{
    const size_t i = ((size_t)blockIdx.x * blockDim.x + threadIdx.x) * 4;
    float4 v = *(const float4*)(src + i);
    __nv_bfloat16 h0 = __float2bfloat16(v.x), h1 = __float2bfloat16(v.y);
    __nv_bfloat16 h2 = __float2bfloat16(v.z), h3 = __float2bfloat16(v.w);
    __nv_bfloat16 l0 = __float2bfloat16(v.x - __bfloat162float(h0));
    __nv_bfloat16 l1 = __float2bfloat16(v.y - __bfloat162float(h1));
    __nv_bfloat16 l2 = __float2bfloat16(v.z - __bfloat162float(h2));
    __nv_bfloat16 l3 = __float2bfloat16(v.w - __bfloat162float(h3));
    *(__nv_bfloat162*)(hi + i)     = __nv_bfloat162(h0, h1);
    *(__nv_bfloat162*)(hi + i + 2) = __nv_bfloat162(h2, h3);
    *(__nv_bfloat162*)(lo + i)     = __nv_bfloat162(l0, l1);
    *(__nv_bfloat162*)(lo + i + 2) = __nv_bfloat162(l2, l3);
}

// ---------------------------------------------------------------------------
// weight transpose + split: w[K,N] fp32 -> hiT/loT [N,K] bf16
// ---------------------------------------------------------------------------
__global__ __launch_bounds__(256) void wsplit_kernel(const float* __restrict__ w,
                                                     __nv_bfloat16* __restrict__ hiT,
                                                     __nv_bfloat16* __restrict__ loT,
                                                     int K, int N)
{
    __shared__ float t[32][33];
    const int k0 = blockIdx.y * 32;
    const int n0 = blockIdx.x * 32;
    const int tx = threadIdx.x, ty = threadIdx.y;
    #pragma unroll
    for (int i = ty; i < 32; i += 8)
        t[i][tx] = w[(size_t)(k0 + i) * N + n0 + tx];
    __syncthreads();
    #pragma unroll
    for (int i = ty; i < 32; i += 8) {
        const float v = t[tx][i];                 // = w[k0+tx][n0+i]
        __nv_bfloat16 h = __float2bfloat16(v);
        __nv_bfloat16 l = __float2bfloat16(v - __bfloat162float(h));
        hiT[(size_t)(n0 + i) * K + k0 + tx] = h;
        loT[(size_t)(n0 + i) * K + k0 + tx] = l;
    }
}

// ---------------------------------------------------------------------------
// Warp-per-token windowed attention; writes split-bf16 (att_hi, att_lo)
// ---------------------------------------------------------------------------
__global__ __launch_bounds__(256) void attn_kernel(const float* __restrict__ x,
                                                   const float* __restrict__ w_width,
                                                   const float* __restrict__ b_width,
                                                   __nv_bfloat16* __restrict__ att_hi,
                                                   __nv_bfloat16* __restrict__ att_lo)
{
    const int gwarp = (blockIdx.x * blockDim.x + threadIdx.x) >> 5;
    const int lane = threadIdx.x & 31;
    if (gwarp >= NTOK) return;

    const int b = gwarp >> 13;            // / LSEQ
    const int l = gwarp & (LSEQ - 1);

    const float* qkv = g_qkv;
    const float* qrow = qkv + (size_t)gwarp * 3 * CDIM;

    float q[16];
    #pragma unroll
    for (int i = 0; i < 16; i++) q[i] = qrow[lane + 32 * i];

    const float* xrow = x + (size_t)gwarp * CDIM;
    float wsum = 0.f;
    #pragma unroll
    for (int i = 0; i < 16; i++)
        wsum += xrow[lane + 32 * i] * w_width[lane + 32 * i];
    #pragma unroll
    for (int o = 16; o > 0; o >>= 1) wsum += __shfl_xor_sync(0xffffffffu, wsum, o);
    const float width = 1.f / (1.f + expf(-(wsum + b_width[0]))) * (float)(KWIN - 1) + 1.f;

    float sc[KWIN];
    #pragma unroll
    for (int j = 0; j < KWIN; j++) {
        const int row = l + j - HALFK;
        float s = 0.f;
        if (row >= 0 && row < LSEQ) {
            const float* krow = qkv + ((size_t)(b * LSEQ + row) * 3 + 1) * CDIM;
            #pragma unroll
            for (int i = 0; i < 16; i++) s += q[i] * krow[lane + 32 * i];
        }
        #pragma unroll
        for (int o = 16; o > 0; o >>= 1) s += __shfl_xor_sync(0xffffffffu, s, o);
        sc[j] = s;
    }

    const float scale = 0.044194173824159216f;
    float mx = -1e30f;
    #pragma unroll
    for (int j = 0; j < KWIN; j++) {
        const float rel = fabsf((float)j - (float)HALFK);
        const float m = 1.f / (1.f + expf(-(width - rel) * 5.f));
        sc[j] = sc[j] * scale - (1.f - m) * 10000.f;
        mx = fmaxf(mx, sc[j]);
    }
    float denom = 0.f;
    #pragma unroll
    for (int j = 0; j < KWIN; j++) {
        sc[j] = expf(sc[j] - mx);
        denom += sc[j];
    }
    const float inv = 1.f / denom;

    float acc[16];
    const float* vself = qkv + ((size_t)gwarp * 3 + 2) * CDIM;
    #pragma unroll
    for (int i = 0; i < 16; i++) acc[i] = vself[lane + 32 * i];

    #pragma unroll
    for (int j = 0; j < KWIN; j++) {
        const int row = l + j - HALFK;
        if (row < 0 || row >= LSEQ) continue;
        const float a = sc[j] * inv;
        const float* vrow = qkv + ((size_t)(b * LSEQ + row) * 3 + 2) * CDIM;
        #pragma unroll
        for (int i = 0; i < 16; i++) acc[i] += a * vrow[lane + 32 * i];
    }

    __nv_bfloat16* hrow = att_hi + (size_t)gwarp * CDIM;
    __nv_bfloat16* lrow = att_lo + (size_t)gwarp * CDIM;
    #pragma unroll
    for (int i = 0; i < 16; i++) {
        const float v = acc[i];
        __nv_bfloat16 h = __float2bfloat16(v);
        hrow[lane + 32 * i] = h;
        lrow[lane + 32 * i] = __float2bfloat16(v - __bfloat162float(h));
    }
}

// ---------------------------------------------------------------------------
extern "C" void kernel_launch(void* const* d_in, const int* in_sizes, int n_in,
                              void* d_out, int out_size)
{
    const float* x       = (const float*)d_in[0];
    const float* w_qkv   = (const float*)d_in[1];
    const float* w_width = (const float*)d_in[2];
    const float* b_width = (const float*)d_in[3];
    const float* w_out   = (const float*)d_in[4];
    float* out = (float*)d_out;

    float* qkv;          cudaGetSymbolAddress((void**)&qkv,  g_qkv);
    __nv_bfloat16* xhi;  cudaGetSymbolAddress((void**)&xhi,  g_xhi);
    __nv_bfloat16* xlo;  cudaGetSymbolAddress((void**)&xlo,  g_xlo);
    __nv_bfloat16* ahi;  cudaGetSymbolAddress((void**)&ahi,  g_ahi);
    __nv_bfloat16* alo;  cudaGetSymbolAddress((void**)&alo,  g_alo);
    __nv_bfloat16* wqhi; cudaGetSymbolAddress((void**)&wqhi, g_wqhi);
    __nv_bfloat16* wqlo; cudaGetSymbolAddress((void**)&wqlo, g_wqlo);
    __nv_bfloat16* wohi; cudaGetSymbolAddress((void**)&wohi, g_wohi);
    __nv_bfloat16* wolo; cudaGetSymbolAddress((void**)&wolo, g_wolo);

    cudaFuncSetAttribute(gemm_mma, cudaFuncAttributeMaxDynamicSharedMemorySize, GEMM_SMEM);

    // 0) input splits
    split_kernel<<<(NTOK * CDIM) / (256 * 4), 256>>>(x, xhi, xlo);
    {
        dim3 g(3 * CDIM / 32, CDIM / 32);
        wsplit_kernel<<<g, dim3(32, 8)>>>(w_qkv, wqhi, wqlo, CDIM, 3 * CDIM);
    }
    {
        dim3 g(CDIM / 32, CDIM / 32);
        wsplit_kernel<<<g, dim3(32, 8)>>>(w_out, wohi, wolo, CDIM, CDIM);
    }

    // 1) qkv = x @ w_qkv   (M=16384, N=1536, K=512)
    {
        dim3 grid(3 * CDIM / 128, NTOK / 128);
        gemm_mma<<<grid, 256, GEMM_SMEM>>>(xhi, xlo, wqhi, wqlo, qkv, 3 * CDIM);
    }

    // 2) fused windowed attention -> att_hi/att_lo (bf16 split)
    attn_kernel<<<NTOK / 8, 256>>>(x, w_width, b_width, ahi, alo);

    // 3) out = att @ w_out  (M=16384, N=512, K=512)
    {
        dim3 grid(CDIM / 128, NTOK / 128);
        gemm_mma<<<grid, 256, GEMM_SMEM>>>(ahi, alo, wohi, wolo, out, CDIM);
    }
}